// round 8
// baseline (speedup 1.0000x reference)
#include <cuda_runtime.h>

// XdGate on site INDEX=3 of an L=8 qutrit (D=3) state vector, N = 3^8 = 6561.
//
// U = I x I x I x M x I x I x I x I with M|i> = |(3-i) mod 3> — a pure
// permutation of the site-3 trit (stride 3^4 = 81):
//   t=0 -> delta 0, t=1 -> +81, t=2 -> -81 (element offsets).
//
// FINAL: launch-overhead bound. Evidence across 7 variants: ncu kernel time
// 3.97-4.54us, issue <=10%, DRAM 0.1%; harness graph-replay timing carries
// +-0.6us noise on an identical binary (5.02 vs 5.63us). Terminal micro-opt:
// 2D block (81, 3) makes the site-3 trit literally threadIdx.y — the tid/81
// reciprocal chain and %3 vanish. idx = blockIdx.x*243 + y*81 + x, exact
// 27-block cover, no guard, no tail. Every remaining instruction is
// load-bearing (S2R x3, ISETP x2, IMAD x2, LDG, STG).
// Vectorized 16B access impossible: src/dst offsets differ by 81 elements
// (4 bytes mod 16). Memcpy decompositions need >=3 graph nodes > 1 kernel.

static constexpr int STRIDE = 81;   // 3^4

__global__ __launch_bounds__(243) void xd_gate_kernel(
    const float* __restrict__ x, float* __restrict__ out) {
    int t = threadIdx.y;                          // site-3 trit, directly: 0,1,2
    int d = (t == 1) - (t == 2);                  // 0 -> 0, 1 -> +1, 2 -> -1
    int idx = blockIdx.x * 243 + t * STRIDE + threadIdx.x;  // exact cover [0,6561)
    out[idx] = x[idx + d * STRIDE];
}

extern "C" void kernel_launch(void* const* d_in, const int* in_sizes, int n_in,
                              void* d_out, int out_size) {
    const float* x = (const float*)d_in[0];   // [6561, 1] float32
    // d_in[1] is M [3,3] — permutation baked in.
    float* out = (float*)d_out;

    dim3 block(81, 3, 1);                     // 243 threads; y = site-3 trit
    xd_gate_kernel<<<27, block>>>(x, out);    // 27 * 243 = 6561 exactly
}